// round 1
// baseline (speedup 1.0000x reference)
#include <cuda_runtime.h>
#include <cuda_bf16.h>

// Problem sizes (fixed by the reference)
#define N_NODES 500000
#define N_ELEM  1000000

// Global double accumulator for Pi = U_internal - W_external.
// Reset each launch by zero_acc_kernel so the graph is replay-safe.
__device__ double g_acc;

__global__ void zero_acc_kernel() {
    g_acc = 0.0;
}

__device__ __forceinline__ double block_reduce_add(double v) {
    __shared__ double warp_sums[32];
    int lane = threadIdx.x & 31;
    int wid  = threadIdx.x >> 5;

    // warp shuffle reduce (double works with __shfl_down_sync)
    #pragma unroll
    for (int off = 16; off > 0; off >>= 1)
        v += __shfl_down_sync(0xFFFFFFFFu, v, off);

    if (lane == 0) warp_sums[wid] = v;
    __syncthreads();

    int nwarps = (blockDim.x + 31) >> 5;
    v = (threadIdx.x < nwarps) ? warp_sums[threadIdx.x] : 0.0;
    if (wid == 0) {
        #pragma unroll
        for (int off = 16; off > 0; off >>= 1)
            v += __shfl_down_sync(0xFFFFFFFFu, v, off);
    }
    return v; // valid in thread 0
}

// Per-element strain energy:
// U = 0.5 * [ EA/L*(uA-uB)^2 + 12*EI/L^3*(wA-wB)^2
//           + 12*EI/L^2*(wA-wB)*(thA+thB)
//           + 4*EI/L*(thA^2 + thB^2 + thA*thB) ]
__global__ void elem_energy_kernel(
    const float* __restrict__ pred,      // [N_NODES,3]
    const float* __restrict__ Lv,        // [N_ELEM]
    const float* __restrict__ Ev,        // [N_ELEM]
    const float* __restrict__ Av,        // [N_ELEM]
    const float* __restrict__ Iv,        // [N_ELEM]
    const float* __restrict__ dir,       // [N_ELEM,3] (c, 0, s)
    const int2*  __restrict__ conn,      // [N_ELEM] (nA, nB)
    const float* __restrict__ u_c_p,
    const float* __restrict__ th_c_p)
{
    const float u_c  = __ldg(u_c_p);
    const float th_c = __ldg(th_c_p);

    int i = blockIdx.x * blockDim.x + threadIdx.x;
    double acc = 0.0;

    if (i < N_ELEM) {
        int2 ab = conn[i];
        float c = __ldg(&dir[3 * i + 0]);
        float s = __ldg(&dir[3 * i + 2]);

        const float* pA = pred + 3 * (long)ab.x;
        const float* pB = pred + 3 * (long)ab.y;
        float a0 = __ldg(&pA[0]) * u_c;
        float a1 = __ldg(&pA[1]) * u_c;
        float thA = __ldg(&pA[2]) * th_c;
        float b0 = __ldg(&pB[0]) * u_c;
        float b1 = __ldg(&pB[1]) * u_c;
        float thB = __ldg(&pB[2]) * th_c;

        float uA =  c * a0 + s * a1;
        float wA = -s * a0 + c * a1;
        float uB =  c * b0 + s * b1;
        float wB = -s * b0 + c * b1;

        float L  = Lv[i];
        float E  = Ev[i];
        float EA = E * Av[i];
        float EI = E * Iv[i];
        float invL = 1.0f / L;
        float ea_L  = EA * invL;
        float ei_L  = EI * invL;
        float ei_L2 = ei_L * invL;
        float ei_L3 = ei_L2 * invL;

        float du = uA - uB;
        float dw = wA - wB;
        float ts = thA + thB;

        float q = ea_L * du * du
                + 12.0f * ei_L3 * dw * dw
                + 12.0f * ei_L2 * dw * ts
                + 4.0f  * ei_L  * (thA * thA + thB * thB + thA * thB);

        acc = 0.5 * (double)q;
    }

    double bsum = block_reduce_add(acc);
    if (threadIdx.x == 0 && bsum != 0.0)
        atomicAdd(&g_acc, bsum);
    else if (threadIdx.x == 0)
        atomicAdd(&g_acc, bsum); // keep work deterministic regardless of value
}

// External work: W = sum(F_ext * u_phys); accumulate -W into g_acc.
__global__ void node_work_kernel(
    const float* __restrict__ pred,   // [N_NODES,3]
    const float* __restrict__ Fext,   // [N_NODES,3]
    const float* __restrict__ u_c_p,
    const float* __restrict__ th_c_p)
{
    const float u_c  = __ldg(u_c_p);
    const float th_c = __ldg(th_c_p);

    int n = blockIdx.x * blockDim.x + threadIdx.x;
    double acc = 0.0;
    if (n < N_NODES) {
        long b = 3 * (long)n;
        float w = Fext[b + 0] * pred[b + 0] * u_c
                + Fext[b + 1] * pred[b + 1] * u_c
                + Fext[b + 2] * pred[b + 2] * th_c;
        acc = -(double)w;
    }
    double bsum = block_reduce_add(acc);
    if (threadIdx.x == 0)
        atomicAdd(&g_acc, bsum);
}

__global__ void finalize_kernel(
    float* __restrict__ out,
    const float* __restrict__ F_c_p,
    const float* __restrict__ u_c_p)
{
    double E_c = fmax((double)__ldg(F_c_p) * (double)__ldg(u_c_p), 1e-30);
    out[0] = (float)(g_acc / E_c);
}

extern "C" void kernel_launch(void* const* d_in, const int* in_sizes, int n_in,
                              void* d_out, int out_size) {
    // metadata order:
    // 0 pred_raw [N_NODES*3] f32
    // 1 elem_lengths [N_ELEM] f32
    // 2 prop_E [N_ELEM] f32
    // 3 prop_A [N_ELEM] f32
    // 4 prop_I22 [N_ELEM] f32
    // 5 elem_directions [N_ELEM*3] f32
    // 6 F_ext [N_NODES*3] f32
    // 7 u_c [1] f32
    // 8 theta_c [1] f32
    // 9 F_c [1] f32
    // 10 connectivity [N_ELEM*2] i32
    const float* pred  = (const float*)d_in[0];
    const float* Lv    = (const float*)d_in[1];
    const float* Ev    = (const float*)d_in[2];
    const float* Av    = (const float*)d_in[3];
    const float* Iv    = (const float*)d_in[4];
    const float* dir   = (const float*)d_in[5];
    const float* Fext  = (const float*)d_in[6];
    const float* u_c   = (const float*)d_in[7];
    const float* th_c  = (const float*)d_in[8];
    const float* F_c   = (const float*)d_in[9];
    const int2*  conn  = (const int2*)d_in[10];
    float* out = (float*)d_out;

    zero_acc_kernel<<<1, 1>>>();

    const int TPB = 256;
    elem_energy_kernel<<<(N_ELEM + TPB - 1) / TPB, TPB>>>(
        pred, Lv, Ev, Av, Iv, dir, conn, u_c, th_c);
    node_work_kernel<<<(N_NODES + TPB - 1) / TPB, TPB>>>(
        pred, Fext, u_c, th_c);

    finalize_kernel<<<1, 1>>>(out, F_c, u_c);
}

// round 2
// speedup vs baseline: 1.3113x; 1.3113x over previous
#include <cuda_runtime.h>
#include <cuda_bf16.h>

#define N_NODES 500000
#define N_ELEM  1000000

#define TPB   256
#define GRID  2072   // 148 SMs * 14

// Per-block partial sums (overwritten every launch) + completion counter
// (reset to 0 by the last block each launch -> graph replay-safe).
__device__ double        g_partials[GRID];
__device__ unsigned int  g_count;   // zero-initialized at module load

__device__ __forceinline__ double block_reduce_add(double v) {
    __shared__ double warp_sums[TPB / 32];
    int lane = threadIdx.x & 31;
    int wid  = threadIdx.x >> 5;

    #pragma unroll
    for (int off = 16; off > 0; off >>= 1)
        v += __shfl_down_sync(0xFFFFFFFFu, v, off);

    if (lane == 0) warp_sums[wid] = v;
    __syncthreads();

    v = (threadIdx.x < (TPB / 32)) ? warp_sums[threadIdx.x] : 0.0;
    if (wid == 0) {
        #pragma unroll
        for (int off = (TPB / 64); off > 0; off >>= 1)
            v += __shfl_down_sync(0xFFFFFFFFu, v, off);
    }
    __syncthreads();   // protect warp_sums for any later reuse
    return v; // valid in thread 0
}

__global__ void __launch_bounds__(TPB)
fused_energy_kernel(
    const float* __restrict__ pred,      // [N_NODES,3]
    const float* __restrict__ Lv,        // [N_ELEM]
    const float* __restrict__ Ev,        // [N_ELEM]
    const float* __restrict__ Av,        // [N_ELEM]
    const float* __restrict__ Iv,        // [N_ELEM]
    const float* __restrict__ dir,       // [N_ELEM,3] (c, 0, s)
    const int2*  __restrict__ conn,      // [N_ELEM] (nA, nB)
    const float* __restrict__ Fext,      // [N_NODES,3]
    const float* __restrict__ u_c_p,
    const float* __restrict__ th_c_p,
    const float* __restrict__ F_c_p,
    float*       __restrict__ out)
{
    const float u_c  = __ldg(u_c_p);
    const float th_c = __ldg(th_c_p);

    const int tid     = blockIdx.x * TPB + threadIdx.x;
    const int nthread = GRID * TPB;

    double acc = 0.0;

    // ---- Element strain energy ----
    // U = 0.5 * [ EA/L*du^2 + 12EI/L^3*dw^2 + 12EI/L^2*dw*(thA+thB)
    //           + 4EI/L*(thA^2 + thB^2 + thA*thB) ]
    for (int i = tid; i < N_ELEM; i += nthread) {
        int2 ab = conn[i];
        float c = __ldg(&dir[3 * i + 0]);
        float s = __ldg(&dir[3 * i + 2]);

        const float* pA = pred + 3 * (long)ab.x;
        const float* pB = pred + 3 * (long)ab.y;
        float a0  = __ldg(&pA[0]) * u_c;
        float a1  = __ldg(&pA[1]) * u_c;
        float thA = __ldg(&pA[2]) * th_c;
        float b0  = __ldg(&pB[0]) * u_c;
        float b1  = __ldg(&pB[1]) * u_c;
        float thB = __ldg(&pB[2]) * th_c;

        float uA =  c * a0 + s * a1;
        float wA = -s * a0 + c * a1;
        float uB =  c * b0 + s * b1;
        float wB = -s * b0 + c * b1;

        float L  = Lv[i];
        float E  = Ev[i];
        float EA = E * Av[i];
        float EI = E * Iv[i];
        float invL  = 1.0f / L;
        float ea_L  = EA * invL;
        float ei_L  = EI * invL;
        float ei_L2 = ei_L * invL;
        float ei_L3 = ei_L2 * invL;

        float du = uA - uB;
        float dw = wA - wB;
        float ts = thA + thB;

        float q = ea_L * du * du
                + 12.0f * ei_L3 * dw * dw
                + 12.0f * ei_L2 * dw * ts
                + 4.0f  * ei_L  * (thA * thA + thB * thB + thA * thB);

        acc += 0.5 * (double)q;
    }

    // ---- External work: -sum(F_ext * u_phys), float4-vectorized ----
    // N_NODES*3 = 1,500,000 floats = 375,000 float4 per array (exact).
    {
        const float4* p4 = (const float4*)pred;
        const float4* f4 = (const float4*)Fext;
        const int NV4 = (N_NODES * 3) / 4;
        for (int j = tid; j < NV4; j += nthread) {
            float4 p = __ldg(&p4[j]);
            float4 f = __ldg(&f4[j]);
            int base = (4 * j) % 3;  // component index of .x
            // scale pattern period 3: [u_c, u_c, th_c]
            float s0 = (base == 2) ? th_c : u_c;
            float s1 = (base == 1) ? th_c : u_c;  // (base+1)%3==2 <=> base==1
            float s2 = (base == 0) ? th_c : u_c;  // (base+2)%3==2 <=> base==0
            float s3 = (base == 2) ? th_c : u_c;  // (base+3)%3 == base
            float w = f.x * p.x * s0 + f.y * p.y * s1
                    + f.z * p.z * s2 + f.w * p.w * s3;
            acc -= (double)w;
        }
    }

    double bsum = block_reduce_add(acc);

    __shared__ bool is_last;
    if (threadIdx.x == 0) {
        g_partials[blockIdx.x] = bsum;
        __threadfence();
        unsigned int done = atomicAdd(&g_count, 1u);
        is_last = (done == GRID - 1);
    }
    __syncthreads();

    if (is_last) {
        // Last block: reduce all partials, finalize, reset counter.
        double v = 0.0;
        for (int b = threadIdx.x; b < GRID; b += TPB)
            v += g_partials[b];
        double total = block_reduce_add(v);
        if (threadIdx.x == 0) {
            double E_c = fmax((double)__ldg(F_c_p) * (double)u_c, 1e-30);
            out[0] = (float)(total / E_c);
            __threadfence();
            g_count = 0;  // replay-safe reset
        }
    }
}

extern "C" void kernel_launch(void* const* d_in, const int* in_sizes, int n_in,
                              void* d_out, int out_size) {
    const float* pred  = (const float*)d_in[0];
    const float* Lv    = (const float*)d_in[1];
    const float* Ev    = (const float*)d_in[2];
    const float* Av    = (const float*)d_in[3];
    const float* Iv    = (const float*)d_in[4];
    const float* dir   = (const float*)d_in[5];
    const float* Fext  = (const float*)d_in[6];
    const float* u_c   = (const float*)d_in[7];
    const float* th_c  = (const float*)d_in[8];
    const float* F_c   = (const float*)d_in[9];
    const int2*  conn  = (const int2*)d_in[10];
    float* out = (float*)d_out;

    fused_energy_kernel<<<GRID, TPB>>>(
        pred, Lv, Ev, Av, Iv, dir, conn, Fext, u_c, th_c, F_c, out);
}

// round 3
// speedup vs baseline: 1.4202x; 1.0830x over previous
#include <cuda_runtime.h>
#include <cuda_bf16.h>

#define N_NODES 500000
#define N_ELEM  1000000
#define N_GROUP (N_ELEM / 4)          // 250000, exact

#define TPB   256
#define GRID  1184   // 148 SMs * 8 -> one resident wave

__device__ double        g_partials[GRID];
__device__ unsigned int  g_count;   // zero-init at load; reset by last block

__device__ __forceinline__ double block_reduce_add(double v) {
    __shared__ double warp_sums[TPB / 32];
    int lane = threadIdx.x & 31;
    int wid  = threadIdx.x >> 5;

    #pragma unroll
    for (int off = 16; off > 0; off >>= 1)
        v += __shfl_down_sync(0xFFFFFFFFu, v, off);

    if (lane == 0) warp_sums[wid] = v;
    __syncthreads();

    v = (threadIdx.x < (TPB / 32)) ? warp_sums[threadIdx.x] : 0.0;
    if (wid == 0) {
        #pragma unroll
        for (int off = (TPB / 64); off > 0; off >>= 1)
            v += __shfl_down_sync(0xFFFFFFFFu, v, off);
    }
    __syncthreads();
    return v; // valid in thread 0
}

__global__ void __launch_bounds__(TPB)
fused_energy_kernel(
    const float* __restrict__ pred,      // [N_NODES,3]
    const float* __restrict__ Lv,        // [N_ELEM]
    const float* __restrict__ Ev,        // [N_ELEM]
    const float* __restrict__ Av,        // [N_ELEM]
    const float* __restrict__ Iv,        // [N_ELEM]
    const float* __restrict__ dir,       // [N_ELEM,3] (c,0,s)
    const int*   __restrict__ conn,      // [N_ELEM,2]
    const float* __restrict__ Fext,      // [N_NODES,3]
    const float* __restrict__ u_c_p,
    const float* __restrict__ th_c_p,
    const float* __restrict__ F_c_p,
    float*       __restrict__ out)
{
    const float u_c  = __ldg(u_c_p);
    const float th_c = __ldg(th_c_p);

    const int tid     = blockIdx.x * TPB + threadIdx.x;
    const int nthread = GRID * TPB;

    double acc = 0.0;

    // ---- Element strain energy, 4 elements per iteration ----
    const int4*   c4 = (const int4*)conn;   // 2 elements per int4
    const float4* L4 = (const float4*)Lv;
    const float4* E4 = (const float4*)Ev;
    const float4* A4 = (const float4*)Av;
    const float4* I4 = (const float4*)Iv;
    const float4* d4 = (const float4*)dir;

    for (int g = tid; g < N_GROUP; g += nthread) {
        // Front-batched independent loads (high MLP)
        int4 cab0 = __ldg(&c4[2 * g + 0]);   // nA0,nB0,nA1,nB1
        int4 cab1 = __ldg(&c4[2 * g + 1]);   // nA2,nB2,nA3,nB3
        float4 Lq = __ldg(&L4[g]);
        float4 Eq = __ldg(&E4[g]);
        float4 Aq = __ldg(&A4[g]);
        float4 Iq = __ldg(&I4[g]);
        float4 D0 = __ldg(&d4[3 * g + 0]);   // c0,0,s0,c1
        float4 D1 = __ldg(&d4[3 * g + 1]);   // 0,s1,c2,0
        float4 D2 = __ldg(&d4[3 * g + 2]);   // s2,c3,0,s3

        int   nA[4] = { cab0.x, cab0.z, cab1.x, cab1.z };
        int   nB[4] = { cab0.y, cab0.w, cab1.y, cab1.w };
        float cc[4] = { D0.x, D0.w, D1.z, D2.y };
        float ss[4] = { D0.z, D1.y, D2.x, D2.w };
        float Ls[4] = { Lq.x, Lq.y, Lq.z, Lq.w };
        float Es[4] = { Eq.x, Eq.y, Eq.z, Eq.w };
        float As[4] = { Aq.x, Aq.y, Aq.z, Aq.w };
        float Is[4] = { Iq.x, Iq.y, Iq.z, Iq.w };

        // Issue all 24 gather loads before any compute
        float a0[4], a1[4], thA[4], b0[4], b1[4], thB[4];
        #pragma unroll
        for (int k = 0; k < 4; k++) {
            const float* pA = pred + 3 * (long)nA[k];
            const float* pB = pred + 3 * (long)nB[k];
            a0[k]  = __ldg(&pA[0]);
            a1[k]  = __ldg(&pA[1]);
            thA[k] = __ldg(&pA[2]);
            b0[k]  = __ldg(&pB[0]);
            b1[k]  = __ldg(&pB[1]);
            thB[k] = __ldg(&pB[2]);
        }

        float qsum = 0.0f;
        #pragma unroll
        for (int k = 0; k < 4; k++) {
            float x0 = a0[k] * u_c,  x1 = a1[k] * u_c,  tA = thA[k] * th_c;
            float y0 = b0[k] * u_c,  y1 = b1[k] * u_c,  tB = thB[k] * th_c;
            float c = cc[k], s = ss[k];

            float uA =  c * x0 + s * x1;
            float wA = -s * x0 + c * x1;
            float uB =  c * y0 + s * y1;
            float wB = -s * y0 + c * y1;

            float E  = Es[k];
            float EA = E * As[k];
            float EI = E * Is[k];
            float invL  = 1.0f / Ls[k];
            float ea_L  = EA * invL;
            float ei_L  = EI * invL;
            float ei_L2 = ei_L * invL;
            float ei_L3 = ei_L2 * invL;

            float du = uA - uB;
            float dw = wA - wB;
            float ts = tA + tB;

            float q = ea_L * du * du
                    + 12.0f * ei_L3 * dw * dw
                    + 12.0f * ei_L2 * dw * ts
                    + 4.0f  * ei_L  * (tA * tA + tB * tB + tA * tB);
            acc += 0.5 * (double)q;
        }
        (void)qsum;
    }

    // ---- External work: -sum(F_ext * u_phys), float4-vectorized ----
    {
        const float4* p4 = (const float4*)pred;
        const float4* f4 = (const float4*)Fext;
        const int NV4 = (N_NODES * 3) / 4;   // 375000, exact
        for (int j = tid; j < NV4; j += nthread) {
            float4 p = __ldg(&p4[j]);
            float4 f = __ldg(&f4[j]);
            int base = (4 * j) % 3;
            float s0 = (base == 2) ? th_c : u_c;
            float s1 = (base == 1) ? th_c : u_c;
            float s2 = (base == 0) ? th_c : u_c;
            float s3 = s0;
            float w = f.x * p.x * s0 + f.y * p.y * s1
                    + f.z * p.z * s2 + f.w * p.w * s3;
            acc -= (double)w;
        }
    }

    double bsum = block_reduce_add(acc);

    __shared__ bool is_last;
    if (threadIdx.x == 0) {
        g_partials[blockIdx.x] = bsum;
        __threadfence();
        unsigned int done = atomicAdd(&g_count, 1u);
        is_last = (done == GRID - 1);
    }
    __syncthreads();

    if (is_last) {
        double v = 0.0;
        for (int b = threadIdx.x; b < GRID; b += TPB)
            v += g_partials[b];
        double total = block_reduce_add(v);
        if (threadIdx.x == 0) {
            double E_c = fmax((double)__ldg(F_c_p) * (double)u_c, 1e-30);
            out[0] = (float)(total / E_c);
            __threadfence();
            g_count = 0;  // replay-safe reset
        }
    }
}

extern "C" void kernel_launch(void* const* d_in, const int* in_sizes, int n_in,
                              void* d_out, int out_size) {
    const float* pred  = (const float*)d_in[0];
    const float* Lv    = (const float*)d_in[1];
    const float* Ev    = (const float*)d_in[2];
    const float* Av    = (const float*)d_in[3];
    const float* Iv    = (const float*)d_in[4];
    const float* dir   = (const float*)d_in[5];
    const float* Fext  = (const float*)d_in[6];
    const float* u_c   = (const float*)d_in[7];
    const float* th_c  = (const float*)d_in[8];
    const float* F_c   = (const float*)d_in[9];
    const int*   conn  = (const int*)d_in[10];
    float* out = (float*)d_out;

    fused_energy_kernel<<<GRID, TPB>>>(
        pred, Lv, Ev, Av, Iv, dir, conn, Fext, u_c, th_c, F_c, out);
}